// round 4
// baseline (speedup 1.0000x reference)
#include <cuda_runtime.h>
#include <math.h>

#define B_    32
#define N_    197
#define C_    384
#define H_    12
#define HD_   32
#define HID_  36
#define NN_   (197*197)          // 38809
#define ROWS_ (B_*N_)            // 6304
#define MLPH_ 1536
#define EPSF  1e-5f
#define SQ_   0.42044820762685725f   // 32^-0.25
#define CNTD  1241888.0              // B*N*N per-channel BN count (double)
#define XSZ_  (ROWS_*C_)             // 2420736
#define ASZ_  (B_*H_*NN_)            // 14902656
#define EHID_ (B_*HID_*NN_)          // 44707968

// ------------------- scratch (device globals; allocation-free rule) ---------
__device__ __align__(16) float g_h  [ROWS_*C_];
__device__ __align__(16) float g_q  [B_*H_*N_*HD_];
__device__ __align__(16) float g_k  [B_*H_*N_*HD_];
__device__ __align__(16) float g_v  [B_*H_*N_*HD_];
__device__ __align__(16) float g_attn0[ASZ_];   // post-softmax attention (a0)
__device__ __align__(16) float g_a  [EHID_];    // conv_exp raw
__device__ __align__(16) float g_act[EHID_];    // activated (bn+relu6) tensor
__device__ __align__(16) float g_bb [EHID_];    // dwconv raw
__device__ __align__(16) float g_c  [ASZ_];     // conv_pro raw -> z -> final attn
__device__ __align__(16) float g_o  [ROWS_*C_];
__device__ __align__(16) float g_x1 [ROWS_*C_];
__device__ __align__(16) float g_h2 [ROWS_*C_];
__device__ __align__(16) float g_m1 [ROWS_*MLPH_];
// fp64 BN stats
__device__ double g_d1s[HID_], g_d1q[HID_];
__device__ double g_d2s[HID_], g_d2q[HID_];
__device__ double g_d3s[H_],   g_d3q[H_];
__device__ double g_d4s[H_],   g_d4q[H_];
// folded affines (alpha[CH], beta[CH])
__device__ float g_ab1[2*HID_];
__device__ float g_ab2[2*HID_];
__device__ float g_ab3[2*H_];
__device__ float g_ab4[2*H_];

// ------------------------------- helpers ------------------------------------
__device__ __forceinline__ float wredsum(float v){
    #pragma unroll
    for (int o = 16; o; o >>= 1) v += __shfl_xor_sync(0xffffffffu, v, o);
    return v;
}
__device__ __forceinline__ float wredmax(float v){
    #pragma unroll
    for (int o = 16; o; o >>= 1) v = fmaxf(v, __shfl_xor_sync(0xffffffffu, v, o));
    return v;
}
__device__ __forceinline__ float clamp6(float v){ return fminf(fmaxf(v, 0.f), 6.f); }
__device__ __forceinline__ float gelu_exact(float v){
    return 0.5f * v * (1.f + erff(v * 0.7071067811865476f));
}

// ------------------------------- kernels ------------------------------------
__global__ void k_zero(){
    int t = threadIdx.x;
    if (t < HID_){ g_d1s[t]=0.0; g_d1q[t]=0.0; g_d2s[t]=0.0; g_d2q[t]=0.0; }
    if (t < H_)  { g_d3s[t]=0.0; g_d3q[t]=0.0; g_d4s[t]=0.0; g_d4q[t]=0.0; }
}

// layernorm(0.5*in) * g + b   (one block per row, 128 threads)
__global__ void k_ln(const float* __restrict__ in, const float* __restrict__ g,
                     const float* __restrict__ b, float* __restrict__ out){
    int row = blockIdx.x;
    const float* p = in + (size_t)row * C_;
    int t = threadIdx.x, w = t >> 5, lane = t & 31;
    float y[3], s = 0.f, sq = 0.f;
    #pragma unroll
    for (int i = 0; i < 3; i++){
        y[i] = 0.5f * p[t + i*128];
        s += y[i]; sq += y[i]*y[i];
    }
    s = wredsum(s); sq = wredsum(sq);
    __shared__ float sh[8];
    if (lane == 0){ sh[w] = s; sh[4+w] = sq; }
    __syncthreads();
    s  = sh[0]+sh[1]+sh[2]+sh[3];
    sq = sh[4]+sh[5]+sh[6]+sh[7];
    float mean = s * (1.f/C_);
    float var  = sq * (1.f/C_) - mean*mean;
    float rs = rsqrtf(var + EPSF);
    #pragma unroll
    for (int i = 0; i < 3; i++){
        int c = t + i*128;
        out[(size_t)row*C_ + c] = (y[i]-mean)*rs*g[c] + b[c];
    }
}

// ------- generic 64x64x16 fp32 GEMM: C = A[M,K] @ W[N,K]^T, variant epilogues
#define V_QKV  0
#define V_PROJ 1
#define V_FC1  2
#define V_FC2  3

template<int VAR>
__global__ __launch_bounds__(256)
void gemm_k(const float* __restrict__ A, const float* __restrict__ W,
            const float* __restrict__ bias, const float* __restrict__ extra,
            const float* __restrict__ resid, float* __restrict__ out,
            int M, int N, int K){
    __shared__ float As[16][68];
    __shared__ float Ws[16][68];
    int tx = threadIdx.x & 15, ty = threadIdx.x >> 4;
    int m0 = blockIdx.y * 64, n0 = blockIdx.x * 64;
    float acc[4][4];
    #pragma unroll
    for (int i = 0; i < 4; i++)
        #pragma unroll
        for (int j = 0; j < 4; j++) acc[i][j] = 0.f;

    int l = threadIdx.x * 4;
    int r = l >> 4, c = l & 15;   // r in [0,64), c in {0,4,8,12}

    for (int k0 = 0; k0 < K; k0 += 16){
        float4 av = make_float4(0.f,0.f,0.f,0.f);
        int gm = m0 + r;
        if (gm < M) av = *(const float4*)(A + (size_t)gm*K + k0 + c);
        As[c+0][r] = av.x; As[c+1][r] = av.y; As[c+2][r] = av.z; As[c+3][r] = av.w;
        float4 wv = *(const float4*)(W + (size_t)(n0 + r)*K + k0 + c);
        Ws[c+0][r] = wv.x; Ws[c+1][r] = wv.y; Ws[c+2][r] = wv.z; Ws[c+3][r] = wv.w;
        __syncthreads();
        #pragma unroll
        for (int kk = 0; kk < 16; kk++){
            float4 a4 = *(float4*)&As[kk][ty*4];
            float4 b4 = *(float4*)&Ws[kk][tx*4];
            float af[4] = {a4.x,a4.y,a4.z,a4.w};
            float bf[4] = {b4.x,b4.y,b4.z,b4.w};
            #pragma unroll
            for (int i = 0; i < 4; i++)
                #pragma unroll
                for (int j = 0; j < 4; j++)
                    acc[i][j] += af[i]*bf[j];
        }
        __syncthreads();
    }

    #pragma unroll
    for (int i = 0; i < 4; i++){
        int gm = m0 + ty*4 + i;
        if (gm >= M) continue;
        #pragma unroll
        for (int j = 0; j < 4; j++){
            int gn = n0 + tx*4 + j;
            float v = acc[i][j];
            if (VAR == V_QKV){
                int which = gn / 384, rr = gn % 384;
                int hh = rr >> 5, dd = rr & 31;
                int bb = gm / N_, np = gm % N_;
                int idx = ((bb*H_ + hh)*N_ + np)*HD_ + dd;
                if (which == 0)      g_q[idx] = v * SQ_;
                else if (which == 1) g_k[idx] = v * SQ_;
                else                 g_v[idx] = v;
            } else if (VAR == V_PROJ){
                out[(size_t)gm*384 + gn] = resid[(size_t)gm*384 + gn] + (v + bias[gn]) * 2.f;
            } else if (VAR == V_FC1){
                out[(size_t)gm*MLPH_ + gn] = gelu_exact(v + bias[gn]);
            } else { // V_FC2
                out[(size_t)gm*384 + gn] = resid[(size_t)gm*384 + gn]
                                         + (v + bias[gn]) * extra[gn] * 2.f;
            }
        }
    }
}

// -------- softmax, literal: one block (256 thr) per (bh, query row) ---------
__global__ __launch_bounds__(256)
void k_softmax_lit(){
    int bh = blockIdx.y, n = blockIdx.x, t = threadIdx.x;
    __shared__ float qs[HD_];
    __shared__ float red[8];
    if (t < HD_) qs[t] = g_q[((size_t)bh*N_ + n)*HD_ + t];
    __syncthreads();
    float v = -1e30f;
    if (t < N_){
        const float* kr = g_k + ((size_t)bh*N_ + t)*HD_;
        float a = 0.f;
        #pragma unroll
        for (int d = 0; d < HD_; d++) a += qs[d]*kr[d];
        v = a;
    }
    float m = wredmax(v);
    if ((t & 31) == 0) red[t >> 5] = m;
    __syncthreads();
    float mx = red[0];
    #pragma unroll
    for (int i = 1; i < 8; i++) mx = fmaxf(mx, red[i]);
    __syncthreads();
    float e = (t < N_) ? __expf(v - mx) : 0.f;
    float s = wredsum(e);
    if ((t & 31) == 0) red[t >> 5] = s;
    __syncthreads();
    float tot = red[0];
    #pragma unroll
    for (int i = 1; i < 8; i++) tot += red[i];
    if (t < N_)
        g_attn0[((size_t)bh*N_ + n)*N_ + t] = e / tot;
}

// -------- conv_exp 12->36 (1x1), literal per-element ------------------------
__global__ __launch_bounds__(256)
void k_conv_exp_lit(const float* __restrict__ wexp){
    int e = blockIdx.x*256 + threadIdx.x;
    if (e >= EHID_) return;
    int p = e % NN_;
    int oc = (e / NN_) % HID_;
    int b  = e / (NN_*HID_);
    const float* in = g_attn0 + (size_t)b*H_*NN_ + p;
    float v = 0.f;
    #pragma unroll
    for (int i = 0; i < H_; i++)
        v += __ldg(&wexp[oc*H_ + i]) * in[(size_t)i*NN_];
    g_a[e] = v;
}

// -------- per-channel BN stats, fp64 (one (b,ch) plane per blockIdx.y) ------
__global__ __launch_bounds__(256)
void k_stats(const float* __restrict__ in, double* __restrict__ ds,
             double* __restrict__ dq, int CH){
    int plane = blockIdx.y;
    int ch = plane % CH;
    const float* p = in + (size_t)plane * NN_;
    int t = threadIdx.x;
    double s = 0.0, sq = 0.0;
    for (int i = blockIdx.x*256 + t; i < NN_; i += gridDim.x*256){
        double v = (double)p[i];
        s += v; sq += v*v;
    }
    __shared__ double sh[256], sh2[256];
    sh[t] = s; sh2[t] = sq;
    __syncthreads();
    for (int o = 128; o; o >>= 1){
        if (t < o){ sh[t] += sh[t+o]; sh2[t] += sh2[t+o]; }
        __syncthreads();
    }
    if (t == 0){
        atomicAdd(&ds[ch], sh[0]);
        atomicAdd(&dq[ch], sh2[0]);
    }
}

// finalize: alpha = g/sqrt(var+eps), beta = b - mean*alpha
template<int NCH>
__global__ void k_find(const float* __restrict__ gg, const float* __restrict__ bb,
                       const double* __restrict__ ds, const double* __restrict__ dq,
                       float* __restrict__ ab){
    int t = threadIdx.x;
    if (t < NCH){
        double m   = ds[t] / CNTD;
        double var = dq[t] / CNTD - m*m;
        double al  = (double)gg[t] / sqrt(var + 1e-5);
        ab[t]       = (float)al;
        ab[NCH + t] = (float)((double)bb[t] - m*al);
    }
}

// bn-affine + relu6, elementwise
__global__ __launch_bounds__(256)
void k_bnact(const float* __restrict__ in, float* __restrict__ out,
             const float* __restrict__ ab, int CH, int total){
    int e = blockIdx.x*256 + threadIdx.x;
    if (e >= total) return;
    int ch = (e / NN_) % CH;
    out[e] = clamp6(ab[ch]*in[e] + ab[CH+ch]);
}

// dw 3x3 SAME, literal per-element
__global__ __launch_bounds__(256)
void k_dw_lit(const float* __restrict__ dww){
    int e = blockIdx.x*256 + threadIdx.x;
    if (e >= EHID_) return;
    int p = e % NN_;
    int c = (e / NN_) % HID_;
    int y = p / N_, x = p % N_;
    const float* in = g_act + (size_t)(e / NN_) * NN_;
    float acc = 0.f;
    #pragma unroll
    for (int ky = 0; ky < 3; ky++){
        int iy = y + ky - 1;
        if (iy < 0 || iy >= N_) continue;
        #pragma unroll
        for (int kx = 0; kx < 3; kx++){
            int ix = x + kx - 1;
            if (ix < 0 || ix >= N_) continue;
            acc += __ldg(&dww[c*9 + ky*3 + kx]) * in[iy*N_ + ix];
        }
    }
    g_bb[e] = acc;
}

// conv_pro 36->12 (1x1), literal per-element
__global__ __launch_bounds__(256)
void k_conv_pro_lit(const float* __restrict__ wpro){
    int e = blockIdx.x*256 + threadIdx.x;
    if (e >= ASZ_) return;
    int p = e % NN_;
    int oc = (e / NN_) % H_;
    int b  = e / (NN_*H_);
    const float* in = g_act + (size_t)b*HID_*NN_ + p;
    float v = 0.f;
    #pragma unroll
    for (int i = 0; i < HID_; i++)
        v += __ldg(&wpro[oc*HID_ + i]) * in[(size_t)i*NN_];
    g_c[e] = v;
}

// z = bn3(c) + a0 (in place)
__global__ __launch_bounds__(256)
void k_z_lit(){
    int e = blockIdx.x*256 + threadIdx.x;
    if (e >= ASZ_) return;
    int ch = (e / NN_) % H_;
    g_c[e] = g_ab3[ch]*g_c[e] + g_ab3[H_+ch] + g_attn0[e];
}

// final attn = abn(z) in place, optionally mirrored into d_out
__global__ __launch_bounds__(256)
void k_abnapply(float* __restrict__ outattn){
    int e = blockIdx.x*256 + threadIdx.x;
    if (e >= ASZ_) return;
    int ch = (e / NN_) % H_;
    float v = g_ab4[ch]*g_c[e] + g_ab4[H_+ch];
    g_c[e] = v;
    if (outattn) outattn[e] = v;
}

// attn @ v, literal: one thread per (bh, n, d)
__global__ __launch_bounds__(256)
void k_av_lit(){
    int idx = blockIdx.x*256 + threadIdx.x;
    if (idx >= B_*H_*N_*HD_) return;
    int d  = idx & (HD_-1);
    int n  = (idx >> 5) % N_;
    int bh = idx / (N_*HD_);
    const float* arow = g_c + ((size_t)bh*N_ + n)*N_;
    const float* vb   = g_v + (size_t)bh*N_*HD_ + d;
    float acc = 0.f;
    for (int m = 0; m < N_; m++)
        acc += arow[m] * vb[(size_t)m*HD_];
    int b = bh / H_, h = bh % H_;
    g_o[((size_t)b*N_ + n)*C_ + h*HD_ + d] = acc;
}

// ------------------------------- launch -------------------------------------
extern "C" void kernel_launch(void* const* d_in, const int* in_sizes, int n_in,
                              void* d_out, int out_size){
    const float* x        = (const float*)d_in[0];
    const float* ln1_g    = (const float*)d_in[1];
    const float* ln1_b    = (const float*)d_in[2];
    const float* qkv_w    = (const float*)d_in[3];
    const float* conv_exp = (const float*)d_in[4];
    const float* bn1_g    = (const float*)d_in[5];
    const float* bn1_b    = (const float*)d_in[6];
    const float* dw_w     = (const float*)d_in[7];
    const float* bn2_g    = (const float*)d_in[8];
    const float* bn2_b    = (const float*)d_in[9];
    const float* conv_pro = (const float*)d_in[10];
    const float* bn3_g    = (const float*)d_in[11];
    const float* bn3_b    = (const float*)d_in[12];
    const float* abn_g    = (const float*)d_in[13];
    const float* abn_b    = (const float*)d_in[14];
    const float* proj_w   = (const float*)d_in[15];
    const float* proj_b   = (const float*)d_in[16];
    const float* ln2_g    = (const float*)d_in[17];
    const float* ln2_b    = (const float*)d_in[18];
    const float* fc1_w    = (const float*)d_in[19];
    const float* fc1_b    = (const float*)d_in[20];
    const float* fc2_w    = (const float*)d_in[21];
    const float* fc2_b    = (const float*)d_in[22];
    const float* scale_ch = (const float*)d_in[23];

    float* out      = (float*)d_out;
    float* out_attn = (out_size >= XSZ_ + ASZ_) ? (out + XSZ_) : nullptr;

    float *p_h, *p_o, *p_x1, *p_h2, *p_m1;
    float *p_a, *p_bb, *p_c, *p_act;
    float *p_ab1, *p_ab2, *p_ab3, *p_ab4;
    double *p_d1s, *p_d1q, *p_d2s, *p_d2q, *p_d3s, *p_d3q, *p_d4s, *p_d4q;
    cudaGetSymbolAddress((void**)&p_h,   g_h);
    cudaGetSymbolAddress((void**)&p_o,   g_o);
    cudaGetSymbolAddress((void**)&p_x1,  g_x1);
    cudaGetSymbolAddress((void**)&p_h2,  g_h2);
    cudaGetSymbolAddress((void**)&p_m1,  g_m1);
    cudaGetSymbolAddress((void**)&p_a,   g_a);
    cudaGetSymbolAddress((void**)&p_bb,  g_bb);
    cudaGetSymbolAddress((void**)&p_c,   g_c);
    cudaGetSymbolAddress((void**)&p_act, g_act);
    cudaGetSymbolAddress((void**)&p_ab1, g_ab1);
    cudaGetSymbolAddress((void**)&p_ab2, g_ab2);
    cudaGetSymbolAddress((void**)&p_ab3, g_ab3);
    cudaGetSymbolAddress((void**)&p_ab4, g_ab4);
    cudaGetSymbolAddress((void**)&p_d1s, g_d1s);
    cudaGetSymbolAddress((void**)&p_d1q, g_d1q);
    cudaGetSymbolAddress((void**)&p_d2s, g_d2s);
    cudaGetSymbolAddress((void**)&p_d2q, g_d2q);
    cudaGetSymbolAddress((void**)&p_d3s, g_d3s);
    cudaGetSymbolAddress((void**)&p_d3q, g_d3q);
    cudaGetSymbolAddress((void**)&p_d4s, g_d4s);
    cudaGetSymbolAddress((void**)&p_d4q, g_d4q);

    const int GB_HID = (EHID_ + 255)/256;   // 174641
    const int GB_A   = (ASZ_  + 255)/256;   // 58214
    const int GB_AV  = (B_*H_*N_*HD_ + 255)/256;

    k_zero<<<1, 64>>>();
    // LN1 + QKV
    k_ln<<<ROWS_, 128>>>(x, ln1_g, ln1_b, p_h);
    gemm_k<V_QKV><<<dim3(18, 99), 256>>>(p_h, qkv_w, nullptr, nullptr, nullptr,
                                         nullptr, ROWS_, 1152, 384);
    // softmax(QK^T) -> a0
    k_softmax_lit<<<dim3(N_, B_*H_), 256>>>();
    // DLA refine, literal
    k_conv_exp_lit<<<GB_HID, 256>>>(conv_exp);
    k_stats<<<dim3(16, B_*HID_), 256>>>(p_a, p_d1s, p_d1q, HID_);
    k_find<HID_><<<1, 64>>>(bn1_g, bn1_b, p_d1s, p_d1q, p_ab1);
    k_bnact<<<GB_HID, 256>>>(p_a, p_act, p_ab1, HID_, EHID_);
    k_dw_lit<<<GB_HID, 256>>>(dw_w);
    k_stats<<<dim3(16, B_*HID_), 256>>>(p_bb, p_d2s, p_d2q, HID_);
    k_find<HID_><<<1, 64>>>(bn2_g, bn2_b, p_d2s, p_d2q, p_ab2);
    k_bnact<<<GB_HID, 256>>>(p_bb, p_act, p_ab2, HID_, EHID_);
    k_conv_pro_lit<<<GB_A, 256>>>(conv_pro);
    k_stats<<<dim3(16, B_*H_), 256>>>(p_c, p_d3s, p_d3q, H_);
    k_find<H_><<<1, 32>>>(bn3_g, bn3_b, p_d3s, p_d3q, p_ab3);
    k_z_lit<<<GB_A, 256>>>();
    k_stats<<<dim3(16, B_*H_), 256>>>(p_c, p_d4s, p_d4q, H_);
    k_find<H_><<<1, 32>>>(abn_g, abn_b, p_d4s, p_d4q, p_ab4);
    k_abnapply<<<GB_A, 256>>>(out_attn);
    // attn @ v, proj + residual
    k_av_lit<<<GB_AV, 256>>>();
    gemm_k<V_PROJ><<<dim3(6, 99), 256>>>(p_o, proj_w, proj_b, nullptr, x,
                                         p_x1, ROWS_, 384, 384);
    // MLP
    k_ln<<<ROWS_, 128>>>(p_x1, ln2_g, ln2_b, p_h2);
    gemm_k<V_FC1><<<dim3(24, 99), 256>>>(p_h2, fc1_w, fc1_b, nullptr, nullptr,
                                         p_m1, ROWS_, MLPH_, 384);
    gemm_k<V_FC2><<<dim3(6, 99), 256>>>(p_m1, fc2_w, fc2_b, scale_ch, p_x1,
                                        out, ROWS_, 384, MLPH_);
}

// round 5
// speedup vs baseline: 1.0290x; 1.0290x over previous
#include <cuda_runtime.h>
#include <math.h>

#define B_    32
#define N_    197
#define C_    384
#define H_    12
#define HD_   32
#define HID_  36
#define NN_   (197*197)          // 38809
#define ROWS_ (B_*N_)            // 6304
#define MLPH_ 1536
#define EPSF  1e-5f
#define SQ_   0.42044820762685725f   // 32^-0.25
#define CNTD  1241888.0              // B*N*N per-channel BN count
#define XSZ_  (ROWS_*C_)             // 2420736
#define ASZ_  (B_*H_*NN_)            // 14902656
#define EHID_ (B_*HID_*NN_)          // 44707968

// ------------------- scratch (device globals; allocation-free rule) ---------
__device__ __align__(16) float g_h  [ROWS_*C_];
__device__ __align__(16) float g_q  [B_*H_*N_*HD_];
__device__ __align__(16) float g_k  [B_*H_*N_*HD_];
__device__ __align__(16) float g_v  [B_*H_*N_*HD_];
__device__ __align__(16) float g_attn0[ASZ_];   // post-softmax attention (a0)
__device__ __align__(16) float g_a  [EHID_];    // conv_exp raw (pre-bn1)
__device__ __align__(16) float g_bb [EHID_];    // dwconv raw (pre-bn2)
__device__ __align__(16) float g_c  [ASZ_];     // conv_pro raw -> z (in place)
__device__ __align__(16) float g_o  [ROWS_*C_];
__device__ __align__(16) float g_x1 [ROWS_*C_];
__device__ __align__(16) float g_h2 [ROWS_*C_];
__device__ __align__(16) float g_m1 [ROWS_*MLPH_];
// fp32 stats (sum | sumsq)
__device__ float g_s1[2*HID_];
__device__ float g_s2[2*HID_];
__device__ float g_s3[2*H_];
__device__ float g_s4[2*H_];
// folded affines (alpha[CH] | beta[CH])
__device__ float g_ab1[2*HID_];
__device__ float g_ab2[2*HID_];
__device__ float g_ab3[2*H_];
__device__ float g_ab4[2*H_];

// ------------------------------- helpers ------------------------------------
__device__ __forceinline__ float wredsum(float v){
    #pragma unroll
    for (int o = 16; o; o >>= 1) v += __shfl_xor_sync(0xffffffffu, v, o);
    return v;
}
__device__ __forceinline__ float wredmax(float v){
    #pragma unroll
    for (int o = 16; o; o >>= 1) v = fmaxf(v, __shfl_xor_sync(0xffffffffu, v, o));
    return v;
}
__device__ __forceinline__ float clamp6(float v){ return fminf(fmaxf(v, 0.f), 6.f); }
__device__ __forceinline__ float gelu_exact(float v){
    return 0.5f * v * (1.f + erff(v * 0.7071067811865476f));
}

// ------------------------------- kernels ------------------------------------
__global__ void k_zero(){
    int t = threadIdx.x;
    if (t < 2*HID_){ g_s1[t] = 0.f; g_s2[t] = 0.f; }
    if (t < 2*H_)  { g_s3[t] = 0.f; g_s4[t] = 0.f; }
}

// layernorm(0.5*in) * g + b   (one block per row, 128 threads)
__global__ void k_ln(const float* __restrict__ in, const float* __restrict__ g,
                     const float* __restrict__ b, float* __restrict__ out){
    int row = blockIdx.x;
    const float* p = in + (size_t)row * C_;
    int t = threadIdx.x, w = t >> 5, lane = t & 31;
    float y[3], s = 0.f, sq = 0.f;
    #pragma unroll
    for (int i = 0; i < 3; i++){
        y[i] = 0.5f * p[t + i*128];
        s += y[i]; sq += y[i]*y[i];
    }
    s = wredsum(s); sq = wredsum(sq);
    __shared__ float sh[8];
    if (lane == 0){ sh[w] = s; sh[4+w] = sq; }
    __syncthreads();
    s  = sh[0]+sh[1]+sh[2]+sh[3];
    sq = sh[4]+sh[5]+sh[6]+sh[7];
    float mean = s * (1.f/C_);
    float var  = sq * (1.f/C_) - mean*mean;
    float rs = rsqrtf(var + EPSF);
    #pragma unroll
    for (int i = 0; i < 3; i++){
        int c = t + i*128;
        out[(size_t)row*C_ + c] = (y[i]-mean)*rs*g[c] + b[c];
    }
}

// ------- generic 64x64x16 fp32 GEMM: C = A[M,K] @ W[N,K]^T, variant epilogues
#define V_QKV  0
#define V_PROJ 1
#define V_FC1  2
#define V_FC2  3

template<int VAR>
__global__ __launch_bounds__(256)
void gemm_k(const float* __restrict__ A, const float* __restrict__ W,
            const float* __restrict__ bias, const float* __restrict__ extra,
            const float* __restrict__ resid, float* __restrict__ out,
            int M, int N, int K){
    __shared__ float As[16][68];
    __shared__ float Ws[16][68];
    int tx = threadIdx.x & 15, ty = threadIdx.x >> 4;
    int m0 = blockIdx.y * 64, n0 = blockIdx.x * 64;
    float acc[4][4];
    #pragma unroll
    for (int i = 0; i < 4; i++)
        #pragma unroll
        for (int j = 0; j < 4; j++) acc[i][j] = 0.f;

    int l = threadIdx.x * 4;
    int r = l >> 4, c = l & 15;   // r in [0,64), c in {0,4,8,12}

    for (int k0 = 0; k0 < K; k0 += 16){
        float4 av = make_float4(0.f,0.f,0.f,0.f);
        int gm = m0 + r;
        if (gm < M) av = *(const float4*)(A + (size_t)gm*K + k0 + c);
        As[c+0][r] = av.x; As[c+1][r] = av.y; As[c+2][r] = av.z; As[c+3][r] = av.w;
        float4 wv = *(const float4*)(W + (size_t)(n0 + r)*K + k0 + c);
        Ws[c+0][r] = wv.x; Ws[c+1][r] = wv.y; Ws[c+2][r] = wv.z; Ws[c+3][r] = wv.w;
        __syncthreads();
        #pragma unroll
        for (int kk = 0; kk < 16; kk++){
            float4 a4 = *(float4*)&As[kk][ty*4];
            float4 b4 = *(float4*)&Ws[kk][tx*4];
            float af[4] = {a4.x,a4.y,a4.z,a4.w};
            float bf[4] = {b4.x,b4.y,b4.z,b4.w};
            #pragma unroll
            for (int i = 0; i < 4; i++)
                #pragma unroll
                for (int j = 0; j < 4; j++)
                    acc[i][j] += af[i]*bf[j];
        }
        __syncthreads();
    }

    #pragma unroll
    for (int i = 0; i < 4; i++){
        int gm = m0 + ty*4 + i;
        if (gm >= M) continue;
        #pragma unroll
        for (int j = 0; j < 4; j++){
            int gn = n0 + tx*4 + j;
            float v = acc[i][j];
            if (VAR == V_QKV){
                int which = gn / 384, rr = gn % 384;
                int hh = rr >> 5, dd = rr & 31;
                int bb = gm / N_, np = gm % N_;
                int idx = ((bb*H_ + hh)*N_ + np)*HD_ + dd;
                if (which == 0)      g_q[idx] = v * SQ_;
                else if (which == 1) g_k[idx] = v * SQ_;
                else                 g_v[idx] = v;
            } else if (VAR == V_PROJ){
                out[(size_t)gm*384 + gn] = resid[(size_t)gm*384 + gn] + (v + bias[gn]) * 2.f;
            } else if (VAR == V_FC1){
                out[(size_t)gm*MLPH_ + gn] = gelu_exact(v + bias[gn]);
            } else { // V_FC2
                out[(size_t)gm*384 + gn] = resid[(size_t)gm*384 + gn]
                                         + (v + bias[gn]) * extra[gn] * 2.f;
            }
        }
    }
}

// ----- attention scores + softmax -> g_attn0 (K staged in shared) -----------
__global__ __launch_bounds__(256)
void k_attn_softmax(){
    __shared__ float ksh[197][33];
    int bh = blockIdx.y, tile = blockIdx.x;
    const float* kb = g_k + (size_t)bh * N_ * HD_;
    for (int idx = threadIdx.x; idx < N_*HD_; idx += 256)
        ksh[idx >> 5][idx & 31] = kb[idx];
    __syncthreads();
    int w = threadIdx.x >> 5, lane = threadIdx.x & 31;
    int rrow = tile*8 + w;
    if (rrow >= N_) return;
    const float* qrow = g_q + ((size_t)bh * N_ + rrow) * HD_;
    float qr[32];
    #pragma unroll
    for (int d = 0; d < 32; d++) qr[d] = qrow[d];

    float sc[7];
    #pragma unroll
    for (int j = 0; j < 7; j++){
        int m = lane + j*32;
        float a = -1e30f;
        if (m < N_){
            a = 0.f;
            #pragma unroll
            for (int d = 0; d < 32; d++) a += qr[d] * ksh[m][d];
        }
        sc[j] = a;
    }
    float mx = sc[0];
    #pragma unroll
    for (int j = 1; j < 7; j++) mx = fmaxf(mx, sc[j]);
    mx = wredmax(mx);
    float sum = 0.f;
    #pragma unroll
    for (int j = 0; j < 7; j++){
        sc[j] = __expf(sc[j] - mx);
        sum += sc[j];
    }
    sum = wredsum(sum);
    float inv = 1.f / sum;
    float* orow = g_attn0 + ((size_t)bh * N_ + rrow) * N_;
    #pragma unroll
    for (int j = 0; j < 7; j++){
        int m = lane + j*32;
        if (m < N_) orow[m] = sc[j] * inv;
    }
}

// ---------------- conv_exp 12->36 (1x1) + bn1 stats (FIXED weight load) -----
__global__ __launch_bounds__(256)
void k_conv_exp(const float* __restrict__ wexp){
    __shared__ float wsh[HID_*H_];
    __shared__ float red[2*HID_];
    for (int i = threadIdx.x; i < HID_*H_; i += 256) wsh[i] = wexp[i];  // FIX
    if (threadIdx.x < 2*HID_) red[threadIdx.x] = 0.f;
    __syncthreads();
    float s[HID_], ss[HID_];
    #pragma unroll
    for (int o = 0; o < HID_; o++){ s[o] = 0.f; ss[o] = 0.f; }
    const int P = B_*NN_;
    for (int p = blockIdx.x*256 + threadIdx.x; p < P; p += gridDim.x*256){
        int b = p / NN_, pp = p - b*NN_;
        const float* in = g_attn0 + (size_t)b*H_*NN_ + pp;
        float av[H_];
        #pragma unroll
        for (int i = 0; i < H_; i++) av[i] = in[(size_t)i*NN_];
        float* op = g_a + (size_t)b*HID_*NN_ + pp;
        #pragma unroll
        for (int o = 0; o < HID_; o++){
            float v = 0.f;
            #pragma unroll
            for (int i = 0; i < H_; i++) v += wsh[o*H_ + i] * av[i];
            op[(size_t)o*NN_] = v;
            s[o] += v; ss[o] += v*v;
        }
    }
    __syncthreads();
    #pragma unroll
    for (int o = 0; o < HID_; o++){
        atomicAdd(&red[o],      s[o]);
        atomicAdd(&red[HID_+o], ss[o]);
    }
    __syncthreads();
    if (threadIdx.x < 2*HID_) atomicAdd(&g_s1[threadIdx.x], red[threadIdx.x]);
}

// finalize a BN (NCH channels): alpha = g/sqrt(var+eps), beta = b - mean*alpha
template<int NCH>
__global__ void k_fin_bn(const float* __restrict__ gg, const float* __restrict__ bb,
                         const float* __restrict__ sums, float* __restrict__ ab){
    int t = threadIdx.x;
    if (t < NCH){
        double m   = (double)sums[t] / CNTD;
        double var = (double)sums[NCH+t] / CNTD - m*m;
        double al  = (double)gg[t] / sqrt(var + 1e-5);
        ab[t]       = (float)al;
        ab[NCH + t] = (float)((double)bb[t] - m*al);
    }
}

// ------------- dw 3x3 (bn1+relu6 applied on the fly) + bn2 stats ------------
__global__ __launch_bounds__(256)
void k_dw(const float* __restrict__ dww){
    int c = blockIdx.y, b = blockIdx.z;
    int tile = blockIdx.x;
    int x0 = (tile % 7) * 32, y0 = (tile / 7) * 8;
    __shared__ float tsh[10][34];
    __shared__ float r2[2];
    if (threadIdx.x < 2) r2[threadIdx.x] = 0.f;
    float al = g_ab1[c], be = g_ab1[HID_+c];
    const float* in = g_a + (size_t)(b*HID_ + c)*NN_;
    for (int idx = threadIdx.x; idx < 340; idx += 256){
        int iy = idx / 34, ix = idx % 34;
        int gy = y0 + iy - 1, gx = x0 + ix - 1;
        float v = 0.f;
        if (gy >= 0 && gy < N_ && gx >= 0 && gx < N_)
            v = clamp6(al * in[gy*N_ + gx] + be);
        tsh[iy][ix] = v;
    }
    __syncthreads();
    float w9[9];
    #pragma unroll
    for (int i = 0; i < 9; i++) w9[i] = __ldg(&dww[c*9 + i]);
    int lx = threadIdx.x & 31, ly = threadIdx.x >> 5;
    int gy = y0 + ly, gx = x0 + lx;
    float acc = 0.f;
    if (gy < N_ && gx < N_){
        #pragma unroll
        for (int ky = 0; ky < 3; ky++)
            #pragma unroll
            for (int kx = 0; kx < 3; kx++)
                acc += w9[ky*3+kx] * tsh[ly+ky][lx+kx];
        g_bb[(size_t)(b*HID_ + c)*NN_ + gy*N_ + gx] = acc;
    }
    float ws = wredsum(acc), wq = wredsum(acc*acc);
    if ((threadIdx.x & 31) == 0){
        atomicAdd(&r2[0], ws);
        atomicAdd(&r2[1], wq);
    }
    __syncthreads();
    if (threadIdx.x == 0){
        atomicAdd(&g_s2[c],       r2[0]);
        atomicAdd(&g_s2[HID_+c],  r2[1]);
    }
}

// ------- conv_pro 36->12 (bn2+relu6 on the fly) -> g_c, + bn3 stats ---------
__global__ __launch_bounds__(256)
void k_conv_pro(const float* __restrict__ wpro){
    __shared__ float wsh[H_*HID_];
    __shared__ float absh[2*HID_];
    __shared__ float red[2*H_];
    for (int i = threadIdx.x; i < H_*HID_; i += 256) wsh[i] = wpro[i];
    if (threadIdx.x < 2*HID_) absh[threadIdx.x] = g_ab2[threadIdx.x];
    if (threadIdx.x < 2*H_) red[threadIdx.x] = 0.f;
    __syncthreads();
    float s[H_], ss[H_];
    #pragma unroll
    for (int o = 0; o < H_; o++){ s[o]=0.f; ss[o]=0.f; }
    const int P = B_*NN_;
    for (int p = blockIdx.x*256 + threadIdx.x; p < P; p += gridDim.x*256){
        int b = p / NN_, pp = p - b*NN_;
        const float* in = g_bb + (size_t)b*HID_*NN_ + pp;
        float rr[HID_];
        #pragma unroll
        for (int i = 0; i < HID_; i++)
            rr[i] = clamp6(absh[i]*in[(size_t)i*NN_] + absh[HID_+i]);
        float* op = g_c + (size_t)b*H_*NN_ + pp;
        #pragma unroll
        for (int o = 0; o < H_; o++){
            float v = 0.f;
            #pragma unroll
            for (int i = 0; i < HID_; i++) v += wsh[o*HID_ + i] * rr[i];
            op[(size_t)o*NN_] = v;
            s[o] += v; ss[o] += v*v;
        }
    }
    __syncthreads();
    #pragma unroll
    for (int o = 0; o < H_; o++){
        atomicAdd(&red[o],    s[o]);
        atomicAdd(&red[H_+o], ss[o]);
    }
    __syncthreads();
    if (threadIdx.x < 2*H_) atomicAdd(&g_s3[threadIdx.x], red[threadIdx.x]);
}

// z = bn3(c) + a0 (in place in g_c), accumulate z stats -----------------------
__global__ __launch_bounds__(256)
void k_z(){
    int bh = blockIdx.y;
    int ch = bh % H_;
    float al = g_ab3[ch], be = g_ab3[H_+ch];
    size_t base = (size_t)bh * NN_;
    float s = 0.f, sq = 0.f;
    for (int p = blockIdx.x*256 + threadIdx.x; p < NN_; p += gridDim.x*256){
        float z = al * g_c[base+p] + be + g_attn0[base+p];
        g_c[base+p] = z;
        s += z; sq += z*z;
    }
    s = wredsum(s); sq = wredsum(sq);
    __shared__ float sh[16];
    int w = threadIdx.x >> 5, lane = threadIdx.x & 31;
    if (lane == 0){ sh[w] = s; sh[8+w] = sq; }
    __syncthreads();
    if (threadIdx.x == 0){
        float S = 0.f, Q = 0.f;
        #pragma unroll
        for (int i = 0; i < 8; i++){ S += sh[i]; Q += sh[8+i]; }
        atomicAdd(&g_s4[ch],     S);
        atomicAdd(&g_s4[H_+ch],  Q);
    }
}

// mirror final attn = abn(z) into d_out (g_c keeps z; av applies affine) -----
__global__ __launch_bounds__(256)
void k_afinal(float* __restrict__ outattn){
    int bh = blockIdx.y;
    int ch = bh % H_;
    float al = g_ab4[ch], be = g_ab4[H_+ch];
    size_t base = (size_t)bh * NN_;
    for (int p = blockIdx.x*256 + threadIdx.x; p < NN_; p += gridDim.x*256)
        outattn[base+p] = al * g_c[base+p] + be;
}

// ---------------- attn @ v (abn affine inline) -> g_o [B,N,384] -------------
__global__ __launch_bounds__(256)
void k_av(){
    __shared__ float vsh[197][32];
    __shared__ float ash[8][197];
    int bh = blockIdx.y, tile = blockIdx.x;
    int ch = bh % H_;
    float al = g_ab4[ch], be = g_ab4[H_+ch];
    const float* vb = g_v + (size_t)bh * N_ * HD_;
    for (int idx = threadIdx.x; idx < N_*HD_; idx += 256)
        vsh[idx >> 5][idx & 31] = vb[idx];
    __syncthreads();
    int w = threadIdx.x >> 5, lane = threadIdx.x & 31;
    int rrow = tile*8 + w;
    if (rrow >= N_) return;
    const float* arow = g_c + ((size_t)bh * N_ + rrow) * N_;
    for (int m = lane; m < N_; m += 32) ash[w][m] = al * arow[m] + be;
    __syncwarp();
    float acc = 0.f;
    #pragma unroll 8
    for (int m = 0; m < N_; m++)
        acc += ash[w][m] * vsh[m][lane];
    int b = bh / H_, h = bh % H_;
    g_o[((size_t)b*N_ + rrow)*C_ + h*HD_ + lane] = acc;
}

// ------------------------------- launch -------------------------------------
extern "C" void kernel_launch(void* const* d_in, const int* in_sizes, int n_in,
                              void* d_out, int out_size){
    const float* x        = (const float*)d_in[0];
    const float* ln1_g    = (const float*)d_in[1];
    const float* ln1_b    = (const float*)d_in[2];
    const float* qkv_w    = (const float*)d_in[3];
    const float* conv_exp = (const float*)d_in[4];
    const float* bn1_g    = (const float*)d_in[5];
    const float* bn1_b    = (const float*)d_in[6];
    const float* dw_w     = (const float*)d_in[7];
    const float* bn2_g    = (const float*)d_in[8];
    const float* bn2_b    = (const float*)d_in[9];
    const float* conv_pro = (const float*)d_in[10];
    const float* bn3_g    = (const float*)d_in[11];
    const float* bn3_b    = (const float*)d_in[12];
    const float* abn_g    = (const float*)d_in[13];
    const float* abn_b    = (const float*)d_in[14];
    const float* proj_w   = (const float*)d_in[15];
    const float* proj_b   = (const float*)d_in[16];
    const float* ln2_g    = (const float*)d_in[17];
    const float* ln2_b    = (const float*)d_in[18];
    const float* fc1_w    = (const float*)d_in[19];
    const float* fc1_b    = (const float*)d_in[20];
    const float* fc2_w    = (const float*)d_in[21];
    const float* fc2_b    = (const float*)d_in[22];
    const float* scale_ch = (const float*)d_in[23];

    float* out      = (float*)d_out;
    float* out_attn = (out_size >= XSZ_ + ASZ_) ? (out + XSZ_) : nullptr;

    float *p_h, *p_o, *p_x1, *p_h2, *p_m1;
    float *p_s1, *p_s2, *p_s3, *p_s4, *p_ab1, *p_ab2, *p_ab3, *p_ab4;
    cudaGetSymbolAddress((void**)&p_h,   g_h);
    cudaGetSymbolAddress((void**)&p_o,   g_o);
    cudaGetSymbolAddress((void**)&p_x1,  g_x1);
    cudaGetSymbolAddress((void**)&p_h2,  g_h2);
    cudaGetSymbolAddress((void**)&p_m1,  g_m1);
    cudaGetSymbolAddress((void**)&p_s1,  g_s1);
    cudaGetSymbolAddress((void**)&p_s2,  g_s2);
    cudaGetSymbolAddress((void**)&p_s3,  g_s3);
    cudaGetSymbolAddress((void**)&p_s4,  g_s4);
    cudaGetSymbolAddress((void**)&p_ab1, g_ab1);
    cudaGetSymbolAddress((void**)&p_ab2, g_ab2);
    cudaGetSymbolAddress((void**)&p_ab3, g_ab3);
    cudaGetSymbolAddress((void**)&p_ab4, g_ab4);

    k_zero<<<1, 128>>>();
    // LN1 + QKV
    k_ln<<<ROWS_, 128>>>(x, ln1_g, ln1_b, p_h);
    gemm_k<V_QKV><<<dim3(18, 99), 256>>>(p_h, qkv_w, nullptr, nullptr, nullptr,
                                         nullptr, ROWS_, 1152, 384);
    // softmax(QK^T)
    k_attn_softmax<<<dim3(25, B_*H_), 256>>>();
    // DLA refine (fused stats/affines)
    k_conv_exp<<<592, 256>>>(conv_exp);
    k_fin_bn<HID_><<<1, 64>>>(bn1_g, bn1_b, p_s1, p_ab1);
    k_dw<<<dim3(175, HID_, B_), 256>>>(dw_w);
    k_fin_bn<HID_><<<1, 64>>>(bn2_g, bn2_b, p_s2, p_ab2);
    k_conv_pro<<<592, 256>>>(conv_pro);
    k_fin_bn<H_><<<1, 32>>>(bn3_g, bn3_b, p_s3, p_ab3);
    k_z<<<dim3(8, B_*H_), 256>>>();
    k_fin_bn<H_><<<1, 32>>>(abn_g, abn_b, p_s4, p_ab4);
    if (out_attn) k_afinal<<<dim3(8, B_*H_), 256>>>(out_attn);
    // attn @ v (abn inline), proj + residual
    k_av<<<dim3(25, B_*H_), 256>>>();
    gemm_k<V_PROJ><<<dim3(6, 99), 256>>>(p_o, proj_w, proj_b, nullptr, x,
                                         p_x1, ROWS_, 384, 384);
    // MLP
    k_ln<<<ROWS_, 128>>>(p_x1, ln2_g, ln2_b, p_h2);
    gemm_k<V_FC1><<<dim3(24, 99), 256>>>(p_h2, fc1_w, fc1_b, nullptr, nullptr,
                                         p_m1, ROWS_, MLPH_, 384);
    gemm_k<V_FC2><<<dim3(6, 99), 256>>>(p_m1, fc2_w, fc2_b, scale_ch, p_x1,
                                        out, ROWS_, 384, MLPH_);
}